// round 5
// baseline (speedup 1.0000x reference)
#include <cuda_runtime.h>
#include <cstdint>

// out[i,j,k] = sum_d x[1+i,d] * x[1+j,d] * Wp[d,k] + b[k]
// (diff_term is antisymmetric -> cancels under symmetrization; prod_term symmetric)
// X: [512,1280] f32, Wp = W[:1280] of W:[2560,2], out: [510,510,2] f32.

namespace {

constexpr int Dd  = 1280;  // feature dim
constexpr int ON  = 510;   // output rows/cols (L-2)
constexpr int TI  = 64;    // i tile
constexpr int TJ  = 32;    // j tile
constexpr int KT  = 32;    // k-chunk
constexpr int SA  = TI + 2; // smem row stride for A tile (pad: 2-way store conflicts, 8B-aligned reads)
constexpr int SB  = TJ + 4; // smem row stride for B tiles (pad, 16B-aligned reads)

__device__ __forceinline__ void fma2(unsigned long long& acc,
                                     unsigned long long a,
                                     unsigned long long b) {
    asm("fma.rn.f32x2 %0, %1, %2, %0;" : "+l"(acc) : "l"(a), "l"(b));
}

__device__ __forceinline__ unsigned long long dup2(unsigned int v) {
    unsigned long long r;
    asm("mov.b64 %0, {%1, %1};" : "=l"(r) : "r"(v));
    return r;
}

__global__ __launch_bounds__(256, 2)
void contact_kernel(const float* __restrict__ x,
                    const float* __restrict__ W,
                    const float* __restrict__ bvec,
                    float* __restrict__ out)
{
    __shared__ float As [KT][SA];  // As[d][i]  (transposed tile)
    __shared__ float Bs0[KT][SB];  // Bs0[d][j] = x[j+1,d]*Wp[d,0]
    __shared__ float Bs1[KT][SB];  // Bs1[d][j] = x[j+1,d]*Wp[d,1]

    const int tid = threadIdx.x;
    const int tx  = tid & 7;    // 8 groups over j (4 j each)
    const int ty  = tid >> 3;   // 32 groups over i (2 i each)

    const int ibase = blockIdx.y * TI;
    const int jbase = blockIdx.x * TJ;

    // acc[k][ii][p] packs output pair (j = 4*tx+2p, 4*tx+2p+1) as f32x2
    unsigned long long acc[2][2][2];
    #pragma unroll
    for (int k = 0; k < 2; ++k)
        #pragma unroll
        for (int ii = 0; ii < 2; ++ii)
            #pragma unroll
            for (int p = 0; p < 2; ++p)
                acc[k][ii][p] = 0ull;

    const float2* __restrict__ W2 = reinterpret_cast<const float2*>(W); // W2[d] = (Wp[d,0], Wp[d,1]) for d<1280

    for (int d0 = 0; d0 < Dd; d0 += KT) {
        // ---- fill A tile: rows ibase..ibase+63 (global row +1), cols d0..d0+31 ----
        #pragma unroll
        for (int it = 0; it < 2; ++it) {
            int idx = tid + it * 256;       // 512 float4 chunks
            int r   = idx >> 3;             // tile row (i)
            int dq  = (idx & 7) * 4;        // col offset within chunk
            float4 v = make_float4(0.f, 0.f, 0.f, 0.f);
            int gi = ibase + r;
            if (gi < ON)
                v = *reinterpret_cast<const float4*>(&x[(size_t)(gi + 1) * Dd + d0 + dq]);
            As[dq + 0][r] = v.x;
            As[dq + 1][r] = v.y;
            As[dq + 2][r] = v.z;
            As[dq + 3][r] = v.w;
        }
        // ---- fill B tiles (scaled by Wp) : rows jbase..jbase+31 ----
        {
            int r  = tid >> 3;              // tile row (j)
            int dq = (tid & 7) * 4;
            float4 v = make_float4(0.f, 0.f, 0.f, 0.f);
            int gj = jbase + r;
            if (gj < ON)
                v = *reinterpret_cast<const float4*>(&x[(size_t)(gj + 1) * Dd + d0 + dq]);
            float2 w0 = W2[d0 + dq + 0];
            float2 w1 = W2[d0 + dq + 1];
            float2 w2 = W2[d0 + dq + 2];
            float2 w3 = W2[d0 + dq + 3];
            Bs0[dq + 0][r] = v.x * w0.x;  Bs1[dq + 0][r] = v.x * w0.y;
            Bs0[dq + 1][r] = v.y * w1.x;  Bs1[dq + 1][r] = v.y * w1.y;
            Bs0[dq + 2][r] = v.z * w2.x;  Bs1[dq + 2][r] = v.z * w2.y;
            Bs0[dq + 3][r] = v.w * w3.x;  Bs1[dq + 3][r] = v.w * w3.y;
        }
        __syncthreads();

        // ---- inner product over this k-chunk: pure FFMA2 ----
        #pragma unroll
        for (int d = 0; d < KT; ++d) {
            // two i values for this thread, each duplicated into an f32x2
            unsigned long long a01 =
                *reinterpret_cast<const unsigned long long*>(&As[d][2 * ty]);
            unsigned int a0u, a1u;
            asm("mov.b64 {%0, %1}, %2;" : "=r"(a0u), "=r"(a1u) : "l"(a01));
            unsigned long long A0 = dup2(a0u);
            unsigned long long A1 = dup2(a1u);

            // four j values per channel, already packed pairwise (LDS.128)
            ulonglong2 B0 = *reinterpret_cast<const ulonglong2*>(&Bs0[d][4 * tx]);
            ulonglong2 B1 = *reinterpret_cast<const ulonglong2*>(&Bs1[d][4 * tx]);

            fma2(acc[0][0][0], A0, B0.x);
            fma2(acc[0][0][1], A0, B0.y);
            fma2(acc[0][1][0], A1, B0.x);
            fma2(acc[0][1][1], A1, B0.y);
            fma2(acc[1][0][0], A0, B1.x);
            fma2(acc[1][0][1], A0, B1.y);
            fma2(acc[1][1][0], A1, B1.x);
            fma2(acc[1][1][1], A1, B1.y);
        }
        __syncthreads();
    }

    // ---- epilogue: add bias, write out[i][j][k] as float2 (k=0,1) ----
    const float b0 = bvec[0];
    const float b1 = bvec[1];

    #pragma unroll
    for (int ii = 0; ii < 2; ++ii) {
        int i = ibase + 2 * ty + ii;
        if (i >= ON) continue;
        #pragma unroll
        for (int p = 0; p < 2; ++p) {
            unsigned int k0e, k0o, k1e, k1o;
            asm("mov.b64 {%0, %1}, %2;" : "=r"(k0e), "=r"(k0o) : "l"(acc[0][ii][p]));
            asm("mov.b64 {%0, %1}, %2;" : "=r"(k1e), "=r"(k1o) : "l"(acc[1][ii][p]));
            int j = jbase + 4 * tx + 2 * p;
            if (j < ON) {
                float2 o = make_float2(__uint_as_float(k0e) + b0,
                                       __uint_as_float(k1e) + b1);
                *reinterpret_cast<float2*>(&out[((size_t)i * ON + j) * 2]) = o;
            }
            if (j + 1 < ON) {
                float2 o = make_float2(__uint_as_float(k0o) + b0,
                                       __uint_as_float(k1o) + b1);
                *reinterpret_cast<float2*>(&out[((size_t)i * ON + j + 1) * 2]) = o;
            }
        }
    }
}

} // namespace

extern "C" void kernel_launch(void* const* d_in, const int* in_sizes, int n_in,
                              void* d_out, int out_size)
{
    const float* x = nullptr;
    const float* W = nullptr;
    const float* b = nullptr;
    for (int i = 0; i < n_in; ++i) {
        if (in_sizes[i] == 512 * 1280)      x = (const float*)d_in[i];
        else if (in_sizes[i] == 2560 * 2)   W = (const float*)d_in[i];
        else if (in_sizes[i] == 2)          b = (const float*)d_in[i];
    }

    dim3 grid((ON + TJ - 1) / TJ,   // 16 j-tiles
              (ON + TI - 1) / TI);  // 8  i-tiles
    contact_kernel<<<grid, 256>>>(x, W, b, (float*)d_out);
}

// round 6
// speedup vs baseline: 1.8213x; 1.8213x over previous
#include <cuda_runtime.h>
#include <cstdint>

// out[i,j,k] = sum_d x[1+i,d] * x[1+j,d] * Wp[d,k] + b[k]
// (diff term is antisymmetric -> cancels under symmetrization; prod term symmetric)
// X: [512,1280] f32, Wp = W[:1280] rows of W:[2560,2], out: [510,510,2] f32.
//
// Strategy: fp32 FFMA2 GEMM-like kernel, D split into 9 z-slices for occupancy,
// partials in __device__ scratch, tiny reduce kernel adds slices + bias.

namespace {

constexpr int Dd  = 1280;
constexpr int ON  = 510;
constexpr int TI  = 128;          // i tile
constexpr int TJ  = 64;           // j tile
constexpr int KT  = 16;           // d chunk
constexpr int SA  = TI + 4;       // smem stride (keeps 16B alignment, spreads banks)
constexpr int SB  = TJ + 4;
constexpr int ZS  = 9;            // D-split slices
constexpr int NCH = Dd / KT;      // 80 chunks total
constexpr int CPZ = (NCH + ZS - 1) / ZS;  // 9 chunks per slice (last gets 8)
constexpr int OUTE = ON * ON * 2; // floats per slice

__device__ float g_scratch[(size_t)ZS * OUTE];  // 18.7 MB partial sums

__device__ __forceinline__ void fma2(unsigned long long& acc,
                                     unsigned long long a,
                                     unsigned long long b) {
    asm("fma.rn.f32x2 %0, %1, %2, %0;" : "+l"(acc) : "l"(a), "l"(b));
}

__device__ __forceinline__ unsigned long long dup2(float v) {
    unsigned long long r;
    unsigned int u = __float_as_uint(v);
    asm("mov.b64 %0, {%1, %1};" : "=l"(r) : "r"(u));
    return r;
}

__global__ __launch_bounds__(256, 2)
void contact_partial_kernel(const float* __restrict__ x,
                            const float* __restrict__ W)
{
    __shared__ float As [KT][SA];  // As[d][i]
    __shared__ float Bs0[KT][SB];  // x[j+1,d]*Wp[d,0]
    __shared__ float Bs1[KT][SB];  // x[j+1,d]*Wp[d,1]

    const int tid = threadIdx.x;
    const int tx  = tid & 15;      // 16 j-groups of 4
    const int ty  = tid >> 4;      // 16 i-groups of 8

    const int ibase = blockIdx.y * TI;
    const int jbase = blockIdx.x * TJ;
    const int z     = blockIdx.z;
    const int c0    = z * CPZ;
    const int c1    = (c0 + CPZ < NCH) ? (c0 + CPZ) : NCH;

    // acc[k][ii][jp]: f32x2 over j-pair (j0+2jp, j0+2jp+1)
    unsigned long long acc[2][8][2];
    #pragma unroll
    for (int k = 0; k < 2; ++k)
        #pragma unroll
        for (int ii = 0; ii < 8; ++ii)
            #pragma unroll
            for (int jp = 0; jp < 2; ++jp)
                acc[k][ii][jp] = 0ull;

    const float2* __restrict__ W2 = reinterpret_cast<const float2*>(W);

    for (int c = c0; c < c1; ++c) {
        const int d0 = c * KT;

        // ---- fill A tile: 128 rows x 16 d (transposed into As[d][i]) ----
        #pragma unroll
        for (int it = 0; it < 2; ++it) {
            int idx = tid + it * 256;       // 512 float4 chunks
            int r   = idx >> 2;             // tile row i (0..127)
            int dq  = (idx & 3) * 4;        // d offset (0,4,8,12)
            float4 v = make_float4(0.f, 0.f, 0.f, 0.f);
            int gi = ibase + r;
            if (gi < ON)
                v = *reinterpret_cast<const float4*>(&x[(size_t)(gi + 1) * Dd + d0 + dq]);
            As[dq + 0][r] = v.x;
            As[dq + 1][r] = v.y;
            As[dq + 2][r] = v.z;
            As[dq + 3][r] = v.w;
        }
        // ---- fill B tiles (Wp folded in): 64 rows x 16 d ----
        {
            int r  = tid >> 2;              // tile row j (0..63)
            int dq = (tid & 3) * 4;
            float4 v = make_float4(0.f, 0.f, 0.f, 0.f);
            int gj = jbase + r;
            if (gj < ON)
                v = *reinterpret_cast<const float4*>(&x[(size_t)(gj + 1) * Dd + d0 + dq]);
            float2 w0 = W2[d0 + dq + 0];
            float2 w1 = W2[d0 + dq + 1];
            float2 w2 = W2[d0 + dq + 2];
            float2 w3 = W2[d0 + dq + 3];
            Bs0[dq + 0][r] = v.x * w0.x;  Bs1[dq + 0][r] = v.x * w0.y;
            Bs0[dq + 1][r] = v.y * w1.x;  Bs1[dq + 1][r] = v.y * w1.y;
            Bs0[dq + 2][r] = v.z * w2.x;  Bs1[dq + 2][r] = v.z * w2.y;
            Bs0[dq + 3][r] = v.w * w3.x;  Bs1[dq + 3][r] = v.w * w3.y;
        }
        __syncthreads();

        // ---- inner product over chunk: 32 FFMA2 per d-step ----
        #pragma unroll
        for (int d = 0; d < KT; ++d) {
            float4 aLo = *reinterpret_cast<const float4*>(&As[d][8 * ty]);
            float4 aHi = *reinterpret_cast<const float4*>(&As[d][8 * ty + 4]);
            unsigned long long A[8];
            A[0] = dup2(aLo.x); A[1] = dup2(aLo.y);
            A[2] = dup2(aLo.z); A[3] = dup2(aLo.w);
            A[4] = dup2(aHi.x); A[5] = dup2(aHi.y);
            A[6] = dup2(aHi.z); A[7] = dup2(aHi.w);

            ulonglong2 B0 = *reinterpret_cast<const ulonglong2*>(&Bs0[d][4 * tx]);
            ulonglong2 B1 = *reinterpret_cast<const ulonglong2*>(&Bs1[d][4 * tx]);

            #pragma unroll
            for (int ii = 0; ii < 8; ++ii) {
                fma2(acc[0][ii][0], A[ii], B0.x);
                fma2(acc[0][ii][1], A[ii], B0.y);
                fma2(acc[1][ii][0], A[ii], B1.x);
                fma2(acc[1][ii][1], A[ii], B1.y);
            }
        }
        __syncthreads();
    }

    // ---- epilogue: write partials (k-interleaved) to this z's scratch slice ----
    float* __restrict__ s = g_scratch + (size_t)z * OUTE;
    const int j0 = jbase + 4 * tx;

    #pragma unroll
    for (int ii = 0; ii < 8; ++ii) {
        int i = ibase + 8 * ty + ii;
        if (i >= ON) continue;
        #pragma unroll
        for (int jp = 0; jp < 2; ++jp) {
            int j = j0 + 2 * jp;
            if (j >= ON) continue;   // j even, ON even -> pair fully in or out
            unsigned int k0e, k0o, k1e, k1o;
            asm("mov.b64 {%0, %1}, %2;" : "=r"(k0e), "=r"(k0o) : "l"(acc[0][ii][jp]));
            asm("mov.b64 {%0, %1}, %2;" : "=r"(k1e), "=r"(k1o) : "l"(acc[1][ii][jp]));
            float4 v = make_float4(__uint_as_float(k0e), __uint_as_float(k1e),
                                   __uint_as_float(k0o), __uint_as_float(k1o));
            *reinterpret_cast<float4*>(&s[((size_t)i * ON + j) * 2]) = v;
        }
    }
}

__global__ void reduce_kernel(const float* __restrict__ bvec,
                              float* __restrict__ out)
{
    int idx = blockIdx.x * 256 + threadIdx.x;   // float2 index
    if (idx >= ON * ON) return;
    float2 acc = make_float2(bvec[0], bvec[1]);
    #pragma unroll
    for (int zz = 0; zz < ZS; ++zz) {
        const float2* p = reinterpret_cast<const float2*>(g_scratch + (size_t)zz * OUTE);
        float2 v = p[idx];
        acc.x += v.x;
        acc.y += v.y;
    }
    reinterpret_cast<float2*>(out)[idx] = acc;
}

} // namespace

extern "C" void kernel_launch(void* const* d_in, const int* in_sizes, int n_in,
                              void* d_out, int out_size)
{
    const float* x = nullptr;
    const float* W = nullptr;
    const float* b = nullptr;
    for (int i = 0; i < n_in; ++i) {
        if (in_sizes[i] == 512 * 1280)      x = (const float*)d_in[i];
        else if (in_sizes[i] == 2560 * 2)   W = (const float*)d_in[i];
        else if (in_sizes[i] == 2)          b = (const float*)d_in[i];
    }

    dim3 grid1((ON + TJ - 1) / TJ,   // 8 j-tiles
               (ON + TI - 1) / TI,   // 4 i-tiles
               ZS);                  // 9 D-slices -> 288 CTAs
    contact_partial_kernel<<<grid1, 256>>>(x, W);

    int nPairs = ON * ON;            // 260100 float2 outputs
    reduce_kernel<<<(nPairs + 255) / 256, 256>>>(b, (float*)d_out);
}

// round 8
// speedup vs baseline: 2.1393x; 1.1746x over previous
#include <cuda_runtime.h>
#include <cstdint>

// out[i,j,k] = sum_d x[1+i,d] * x[1+j,d] * Wp[d,k] + b[k]   (symmetric in i,j)
// X: [512,1280] f32, Wp = W[:1280] of W:[2560,2], out: [510,510,2] f32.
//
// Pipeline:
//  1) prep_kernel: transpose + scale + pad:
//       g_xT [d][l] = x[l+1][d]          (l<511, else 0)   [1280 x 520]
//       g_xb0[d][l] = x[l+1][d]*Wp[d,0]
//       g_xb1[d][l] = x[l+1][d]*Wp[d,1]
//  2) contact_sym_kernel: symmetric tiles (ti>=tj), 64x64, D split into 8
//     z-slices; cp.async double-buffered fills; partials to g_part.
//  3) reduce_kernel: sum 8 slices (reading transposed tile for i<j), add bias.

namespace {

constexpr int Dd   = 1280;
constexpr int ON   = 510;
constexpr int XTW  = 520;             // padded width of transposed arrays
constexpr int TS   = 64;              // tile size (i and j)
constexpr int KT   = 16;              // d per chunk
constexpr int SSTR = TS + 4;          // smem row stride (68 floats)
constexpr int ZS   = 8;               // D slices (160 d each)
constexpr int DPZ  = Dd / ZS;         // 160
constexpr int NCH  = DPZ / KT;        // 10 chunks per slice
constexpr int NT   = 36;              // triangular tiles over 8x8 grid
constexpr int TILE_ELEMS = TS * TS * 2;  // 8192 floats per tile partial

__device__ float g_xT [Dd * XTW];
__device__ float g_xb0[Dd * XTW];
__device__ float g_xb1[Dd * XTW];
__device__ float g_part[(size_t)ZS * NT * TILE_ELEMS];   // 9.4 MB

__device__ __forceinline__ void fma2(unsigned long long& acc,
                                     unsigned long long a,
                                     unsigned long long b) {
    asm("fma.rn.f32x2 %0, %1, %2, %0;" : "+l"(acc) : "l"(a), "l"(b));
}

__device__ __forceinline__ unsigned long long dup2(float v) {
    unsigned long long r;
    unsigned int u = __float_as_uint(v);
    asm("mov.b64 %0, {%1, %1};" : "=l"(r) : "r"(u));
    return r;
}

__device__ __forceinline__ void cpa16(uint32_t smem_addr, const float* g) {
    asm volatile("cp.async.cg.shared.global [%0], [%1], 16;"
                 :: "r"(smem_addr), "l"(g));
}

// ---------------- prep: transpose + scale + zero-pad ----------------
__global__ __launch_bounds__(256)
void prep_kernel(const float* __restrict__ x, const float* __restrict__ W)
{
    __shared__ float tile[32][33];
    const int d0 = blockIdx.x * 32;
    const int l0 = blockIdx.y * 32;
    const int tx = threadIdx.x & 31;
    const int ty = threadIdx.x >> 5;     // 0..7

    #pragma unroll
    for (int r = 0; r < 4; ++r) {
        int l = l0 + ty + 8 * r;
        tile[ty + 8 * r][tx] = x[(size_t)l * Dd + d0 + tx];
    }
    __syncthreads();

    const float2* __restrict__ W2 = reinterpret_cast<const float2*>(W);

    #pragma unroll
    for (int r = 0; r < 4; ++r) {
        int d = d0 + ty + 8 * r;
        int l = l0 + tx;
        if (l >= 1) {
            float  v = tile[tx][ty + 8 * r];     // = x[l][d]
            float2 w = W2[d];
            size_t o = (size_t)d * XTW + (l - 1);
            g_xT [o] = v;
            g_xb0[o] = v * w.x;
            g_xb1[o] = v * w.y;
        }
    }

    // zero pad columns 511..519 for this block's 32 d-rows
    if (blockIdx.y == 15 && threadIdx.x < 32 * 9) {
        int dd = threadIdx.x / 9;
        int cc = 511 + threadIdx.x % 9;
        size_t o = (size_t)(d0 + dd) * XTW + cc;
        g_xT [o] = 0.f;
        g_xb0[o] = 0.f;
        g_xb1[o] = 0.f;
    }
}

// ---------------- main symmetric GEMM ----------------
__global__ __launch_bounds__(256, 2)
void contact_sym_kernel()
{
    __shared__ float smA [2][KT][SSTR];
    __shared__ float smB0[2][KT][SSTR];
    __shared__ float smB1[2][KT][SSTR];

    const int tid = threadIdx.x;
    const int tx  = tid & 15;       // 16 j-groups of 4
    const int ty  = tid >> 4;       // 16 i-groups of 4

    // decode triangular tile id -> (ti, tj), ti >= tj
    int rem = blockIdx.x, ti = 0;
    while (rem > ti) { rem -= (ti + 1); ti++; }
    const int tj = rem;
    const int z  = blockIdx.y;

    const int ibase = ti * TS;
    const int jbase = tj * TS;
    const int dbase = z * DPZ;

    // fill addresses for this thread: one 16B chunk per array per chunk-load
    const int frow = tid >> 4;           // 0..15 (d within chunk)
    const int fq   = (tid & 15) * 4;     // 0,4,..,60 (col)
    const float* srcA  = g_xT  + (size_t)(dbase + frow) * XTW + ibase + fq;
    const float* srcB0 = g_xb0 + (size_t)(dbase + frow) * XTW + jbase + fq;
    const float* srcB1 = g_xb1 + (size_t)(dbase + frow) * XTW + jbase + fq;
    const size_t cstep = (size_t)KT * XTW;

    uint32_t dA [2], dB0[2], dB1[2];
    #pragma unroll
    for (int p = 0; p < 2; ++p) {
        dA [p] = (uint32_t)__cvta_generic_to_shared(&smA [p][frow][fq]);
        dB0[p] = (uint32_t)__cvta_generic_to_shared(&smB0[p][frow][fq]);
        dB1[p] = (uint32_t)__cvta_generic_to_shared(&smB1[p][frow][fq]);
    }

    unsigned long long acc[2][4][2];
    #pragma unroll
    for (int k = 0; k < 2; ++k)
        #pragma unroll
        for (int ii = 0; ii < 4; ++ii)
            #pragma unroll
            for (int jp = 0; jp < 2; ++jp)
                acc[k][ii][jp] = 0ull;

    // prefetch chunk 0
    cpa16(dA[0],  srcA);
    cpa16(dB0[0], srcB0);
    cpa16(dB1[0], srcB1);
    asm volatile("cp.async.commit_group;" ::: "memory");

    for (int c = 0; c < NCH; ++c) {
        if (c + 1 < NCH) {
            int nb = (c + 1) & 1;
            const float* a  = srcA  + (size_t)(c + 1) * cstep;
            const float* b0 = srcB0 + (size_t)(c + 1) * cstep;
            const float* b1 = srcB1 + (size_t)(c + 1) * cstep;
            cpa16(dA[nb],  a);
            cpa16(dB0[nb], b0);
            cpa16(dB1[nb], b1);
            asm volatile("cp.async.commit_group;" ::: "memory");
            asm volatile("cp.async.wait_group 1;" ::: "memory");
        } else {
            asm volatile("cp.async.wait_group 0;" ::: "memory");
        }
        __syncthreads();

        const int cb = c & 1;
        #pragma unroll
        for (int d = 0; d < KT; ++d) {
            float4 av = *reinterpret_cast<const float4*>(&smA[cb][d][4 * ty]);
            unsigned long long A0 = dup2(av.x);
            unsigned long long A1 = dup2(av.y);
            unsigned long long A2 = dup2(av.z);
            unsigned long long A3 = dup2(av.w);

            ulonglong2 B0 = *reinterpret_cast<const ulonglong2*>(&smB0[cb][d][4 * tx]);
            ulonglong2 B1 = *reinterpret_cast<const ulonglong2*>(&smB1[cb][d][4 * tx]);

            fma2(acc[0][0][0], A0, B0.x);  fma2(acc[0][0][1], A0, B0.y);
            fma2(acc[0][1][0], A1, B0.x);  fma2(acc[0][1][1], A1, B0.y);
            fma2(acc[0][2][0], A2, B0.x);  fma2(acc[0][2][1], A2, B0.y);
            fma2(acc[0][3][0], A3, B0.x);  fma2(acc[0][3][1], A3, B0.y);
            fma2(acc[1][0][0], A0, B1.x);  fma2(acc[1][0][1], A0, B1.y);
            fma2(acc[1][1][0], A1, B1.x);  fma2(acc[1][1][1], A1, B1.y);
            fma2(acc[1][2][0], A2, B1.x);  fma2(acc[1][2][1], A2, B1.y);
            fma2(acc[1][3][0], A3, B1.x);  fma2(acc[1][3][1], A3, B1.y);
        }
        __syncthreads();
    }

    // epilogue: partials to scratch, k-interleaved [li][lj][k]
    float* __restrict__ s = g_part + ((size_t)z * NT + blockIdx.x) * TILE_ELEMS;
    const int lj0 = 4 * tx;
    #pragma unroll
    for (int ii = 0; ii < 4; ++ii) {
        const int li = 4 * ty + ii;
        #pragma unroll
        for (int jp = 0; jp < 2; ++jp) {
            unsigned int k0e, k0o, k1e, k1o;
            asm("mov.b64 {%0, %1}, %2;" : "=r"(k0e), "=r"(k0o) : "l"(acc[0][ii][jp]));
            asm("mov.b64 {%0, %1}, %2;" : "=r"(k1e), "=r"(k1o) : "l"(acc[1][ii][jp]));
            float4 v = make_float4(__uint_as_float(k0e), __uint_as_float(k1e),
                                   __uint_as_float(k0o), __uint_as_float(k1o));
            *reinterpret_cast<float4*>(&s[((size_t)li * TS + lj0 + 2 * jp) * 2]) = v;
        }
    }
}

// ---------------- reduce: sum slices + mirror + bias ----------------
__global__ __launch_bounds__(256)
void reduce_kernel(const float* __restrict__ bvec, float* __restrict__ out)
{
    const int j = blockIdx.x * 256 + threadIdx.x;
    const int i = blockIdx.y;
    if (j >= ON) return;

    const int ti = i >> 6, li = i & 63;
    const int tj = j >> 6, lj = j & 63;

    int tile, idx;
    if (ti >= tj) { tile = (ti * (ti + 1)) / 2 + tj; idx = li * TS + lj; }
    else          { tile = (tj * (tj + 1)) / 2 + ti; idx = lj * TS + li; }

    float2 acc = make_float2(bvec[0], bvec[1]);
    #pragma unroll
    for (int z = 0; z < ZS; ++z) {
        const float2* p = reinterpret_cast<const float2*>(
            g_part + ((size_t)z * NT + tile) * TILE_ELEMS);
        float2 v = p[idx];
        acc.x += v.x;
        acc.y += v.y;
    }
    reinterpret_cast<float2*>(out)[(size_t)i * ON + j] = acc;
}

} // namespace

extern "C" void kernel_launch(void* const* d_in, const int* in_sizes, int n_in,
                              void* d_out, int out_size)
{
    const float* x = nullptr;
    const float* W = nullptr;
    const float* b = nullptr;
    for (int i = 0; i < n_in; ++i) {
        if (in_sizes[i] == 512 * 1280)      x = (const float*)d_in[i];
        else if (in_sizes[i] == 2560 * 2)   W = (const float*)d_in[i];
        else if (in_sizes[i] == 2)          b = (const float*)d_in[i];
    }

    prep_kernel<<<dim3(Dd / 32, 512 / 32), 256>>>(x, W);          // 40 x 16
    contact_sym_kernel<<<dim3(NT, ZS), 256>>>();                  // 36 x 8 = 288
    reduce_kernel<<<dim3(2, ON), 256>>>(b, (float*)d_out);        // 1020 blocks
}

// round 9
// speedup vs baseline: 2.1558x; 1.0077x over previous
#include <cuda_runtime.h>
#include <cstdint>

// out[i,j,k] = sum_d x[1+i,d] * x[1+j,d] * Wp[d,k] + b[k]   (symmetric in i,j)
// X: [512,1280] f32, Wp = W[:1280] of W:[2560,2], out: [510,510,2] f32.
//
// Pipeline:
//  1) prep_kernel: direct transpose+scale+pad (no smem):
//       g_xT [d][l] = x[l+1][d] (l<510 else 0), g_xb0 = *Wp[d,0], g_xb1 = *Wp[d,1]
//  2) contact_sym_kernel: triangular 64x64 tiles (ti>=tj), D split into 8
//     z-slices, cp.async double-buffered, FFMA2 inner loop, partials to g_part.
//  3) reduce_kernel: tile-blocked slice sum + mirror (smem transpose) + bias.

namespace {

constexpr int Dd   = 1280;
constexpr int ON   = 510;
constexpr int XTW  = 520;             // padded width of transposed arrays
constexpr int TS   = 64;              // tile size
constexpr int KT   = 16;              // d per chunk
constexpr int SSTR = TS + 4;          // smem row stride
constexpr int ZS   = 8;               // D slices (160 d each)
constexpr int DPZ  = Dd / ZS;
constexpr int NCH  = DPZ / KT;        // 10
constexpr int NT   = 36;              // triangular tiles over 8x8
constexpr int TILE_ELEMS = TS * TS * 2;

__device__ float g_xT [Dd * XTW];
__device__ float g_xb0[Dd * XTW];
__device__ float g_xb1[Dd * XTW];
__device__ float g_part[(size_t)ZS * NT * TILE_ELEMS];   // 9.4 MB

__device__ __forceinline__ void fma2(unsigned long long& acc,
                                     unsigned long long a,
                                     unsigned long long b) {
    asm("fma.rn.f32x2 %0, %1, %2, %0;" : "+l"(acc) : "l"(a), "l"(b));
}

__device__ __forceinline__ unsigned long long dup2(float v) {
    unsigned long long r;
    unsigned int u = __float_as_uint(v);
    asm("mov.b64 %0, {%1, %1};" : "=l"(r) : "r"(u));
    return r;
}

__device__ __forceinline__ void cpa16(uint32_t smem_addr, const float* g) {
    asm volatile("cp.async.cg.shared.global [%0], [%1], 16;"
                 :: "r"(smem_addr), "l"(g));
}

// ---------------- prep: direct transpose + scale + pad (no smem) ----------------
__global__ __launch_bounds__(256)
void prep_kernel(const float* __restrict__ x, const float* __restrict__ W)
{
    const int gid = blockIdx.x * 256 + threadIdx.x;   // 0 .. 1280*130-1
    const int d   = gid / 130;
    const int lq  = gid - d * 130;                    // float4 col group
    const int l   = lq * 4;

    // gather 4 values down column d of x (rows l+1 .. l+4), zero past 509
    float v[4];
    #pragma unroll
    for (int q = 0; q < 4; ++q) {
        int lc = l + q;
        v[q] = (lc < ON) ? x[(size_t)(lc + 1) * Dd + d] : 0.f;
    }

    const float2 w = reinterpret_cast<const float2*>(W)[d];
    const size_t o = (size_t)d * XTW + l;

    *reinterpret_cast<float4*>(&g_xT [o]) = make_float4(v[0], v[1], v[2], v[3]);
    *reinterpret_cast<float4*>(&g_xb0[o]) = make_float4(v[0]*w.x, v[1]*w.x, v[2]*w.x, v[3]*w.x);
    *reinterpret_cast<float4*>(&g_xb1[o]) = make_float4(v[0]*w.y, v[1]*w.y, v[2]*w.y, v[3]*w.y);
}

// ---------------- main symmetric GEMM (unchanged from R8) ----------------
__global__ __launch_bounds__(256, 2)
void contact_sym_kernel()
{
    __shared__ float smA [2][KT][SSTR];
    __shared__ float smB0[2][KT][SSTR];
    __shared__ float smB1[2][KT][SSTR];

    const int tid = threadIdx.x;
    const int tx  = tid & 15;
    const int ty  = tid >> 4;

    int rem = blockIdx.x, ti = 0;
    while (rem > ti) { rem -= (ti + 1); ti++; }
    const int tj = rem;
    const int z  = blockIdx.y;

    const int ibase = ti * TS;
    const int jbase = tj * TS;
    const int dbase = z * DPZ;

    const int frow = tid >> 4;
    const int fq   = (tid & 15) * 4;
    const float* srcA  = g_xT  + (size_t)(dbase + frow) * XTW + ibase + fq;
    const float* srcB0 = g_xb0 + (size_t)(dbase + frow) * XTW + jbase + fq;
    const float* srcB1 = g_xb1 + (size_t)(dbase + frow) * XTW + jbase + fq;
    const size_t cstep = (size_t)KT * XTW;

    uint32_t dA [2], dB0[2], dB1[2];
    #pragma unroll
    for (int p = 0; p < 2; ++p) {
        dA [p] = (uint32_t)__cvta_generic_to_shared(&smA [p][frow][fq]);
        dB0[p] = (uint32_t)__cvta_generic_to_shared(&smB0[p][frow][fq]);
        dB1[p] = (uint32_t)__cvta_generic_to_shared(&smB1[p][frow][fq]);
    }

    unsigned long long acc[2][4][2];
    #pragma unroll
    for (int k = 0; k < 2; ++k)
        #pragma unroll
        for (int ii = 0; ii < 4; ++ii)
            #pragma unroll
            for (int jp = 0; jp < 2; ++jp)
                acc[k][ii][jp] = 0ull;

    cpa16(dA[0],  srcA);
    cpa16(dB0[0], srcB0);
    cpa16(dB1[0], srcB1);
    asm volatile("cp.async.commit_group;" ::: "memory");

    for (int c = 0; c < NCH; ++c) {
        if (c + 1 < NCH) {
            int nb = (c + 1) & 1;
            cpa16(dA[nb],  srcA  + (size_t)(c + 1) * cstep);
            cpa16(dB0[nb], srcB0 + (size_t)(c + 1) * cstep);
            cpa16(dB1[nb], srcB1 + (size_t)(c + 1) * cstep);
            asm volatile("cp.async.commit_group;" ::: "memory");
            asm volatile("cp.async.wait_group 1;" ::: "memory");
        } else {
            asm volatile("cp.async.wait_group 0;" ::: "memory");
        }
        __syncthreads();

        const int cb = c & 1;
        #pragma unroll
        for (int d = 0; d < KT; ++d) {
            float4 av = *reinterpret_cast<const float4*>(&smA[cb][d][4 * ty]);
            unsigned long long A0 = dup2(av.x);
            unsigned long long A1 = dup2(av.y);
            unsigned long long A2 = dup2(av.z);
            unsigned long long A3 = dup2(av.w);

            ulonglong2 B0 = *reinterpret_cast<const ulonglong2*>(&smB0[cb][d][4 * tx]);
            ulonglong2 B1 = *reinterpret_cast<const ulonglong2*>(&smB1[cb][d][4 * tx]);

            fma2(acc[0][0][0], A0, B0.x);  fma2(acc[0][0][1], A0, B0.y);
            fma2(acc[0][1][0], A1, B0.x);  fma2(acc[0][1][1], A1, B0.y);
            fma2(acc[0][2][0], A2, B0.x);  fma2(acc[0][2][1], A2, B0.y);
            fma2(acc[0][3][0], A3, B0.x);  fma2(acc[0][3][1], A3, B0.y);
            fma2(acc[1][0][0], A0, B1.x);  fma2(acc[1][0][1], A0, B1.y);
            fma2(acc[1][1][0], A1, B1.x);  fma2(acc[1][1][1], A1, B1.y);
            fma2(acc[1][2][0], A2, B1.x);  fma2(acc[1][2][1], A2, B1.y);
            fma2(acc[1][3][0], A3, B1.x);  fma2(acc[1][3][1], A3, B1.y);
        }
        __syncthreads();
    }

    float* __restrict__ s = g_part + ((size_t)z * NT + blockIdx.x) * TILE_ELEMS;
    const int lj0 = 4 * tx;
    #pragma unroll
    for (int ii = 0; ii < 4; ++ii) {
        const int li = 4 * ty + ii;
        #pragma unroll
        for (int jp = 0; jp < 2; ++jp) {
            unsigned int k0e, k0o, k1e, k1o;
            asm("mov.b64 {%0, %1}, %2;" : "=r"(k0e), "=r"(k0o) : "l"(acc[0][ii][jp]));
            asm("mov.b64 {%0, %1}, %2;" : "=r"(k1e), "=r"(k1o) : "l"(acc[1][ii][jp]));
            float4 v = make_float4(__uint_as_float(k0e), __uint_as_float(k1e),
                                   __uint_as_float(k0o), __uint_as_float(k1o));
            *reinterpret_cast<float4*>(&s[((size_t)li * TS + lj0 + 2 * jp) * 2]) = v;
        }
    }
}

// ---------------- reduce: tile-blocked slice sum + mirror + bias ----------------
// grid = (2 halves, 64 output tiles); block = 256 threads.
// straight (oti>=otj): float4 read/acc/write, fully coalesced.
// mirror  (oti<otj):   coalesced float4 reads of source tile, acc over z,
//                      smem transpose, coalesced float4 writes.
__global__ __launch_bounds__(256)
void reduce_kernel(const float* __restrict__ bvec, float* __restrict__ out)
{
    __shared__ float2 sm[32][67];    // padded transpose buffer (mirror path)

    const int t   = threadIdx.x;
    const int h   = blockIdx.x;            // 0/1: row half
    const int ot  = blockIdx.y;            // output tile id
    const int oti = ot >> 3;
    const int otj = ot & 7;

    const float b0 = bvec[0];
    const float b1 = bvec[1];

    if (oti >= otj) {
        // straight: source tile (oti,otj), same orientation
        const int src = (oti * (oti + 1)) / 2 + otj;
        const float* base = g_part + (size_t)src * TILE_ELEMS;
        #pragma unroll
        for (int r = 0; r < 4; ++r) {
            int fp = t + 256 * r;                 // float4 idx within half (1024)
            int a  = h * 32 + (fp >> 5);          // row li
            int lj = (fp & 31) * 2;               // col pair
            size_t off = ((size_t)a * TS + lj) * 2;

            float4 acc = make_float4(b0, b1, b0, b1);
            #pragma unroll
            for (int z = 0; z < ZS; ++z) {
                float4 v = *reinterpret_cast<const float4*>(
                    base + (size_t)z * NT * TILE_ELEMS + off);
                acc.x += v.x; acc.y += v.y; acc.z += v.z; acc.w += v.w;
            }
            int i = oti * TS + a;
            int j = otj * TS + lj;
            if (i < ON && j < ON)
                *reinterpret_cast<float4*>(&out[((size_t)i * ON + j) * 2]) = acc;
        }
    } else {
        // mirror: source tile (otj,oti); out[li][lj] = src[lj][li]
        const int src = (otj * (otj + 1)) / 2 + oti;
        const float* base = g_part + (size_t)src * TILE_ELEMS;
        #pragma unroll
        for (int r = 0; r < 4; ++r) {
            int fp = t + 256 * r;                 // 1024 float4 per half
            int b  = fp >> 4;                     // src row (= out col lj), 0..63
            int c  = fp & 15;                     // col-pair group within half
            int a0 = h * 32 + c * 2;              // src cols (= out rows li)
            size_t off = ((size_t)b * TS + a0) * 2;

            float4 acc = make_float4(b0, b1, b0, b1);
            #pragma unroll
            for (int z = 0; z < ZS; ++z) {
                float4 v = *reinterpret_cast<const float4*>(
                    base + (size_t)z * NT * TILE_ELEMS + off);
                acc.x += v.x; acc.y += v.y; acc.z += v.z; acc.w += v.w;
            }
            // transpose through smem: sm[li_local][lj]
            sm[c * 2 + 0][b] = make_float2(acc.x, acc.y);
            sm[c * 2 + 1][b] = make_float2(acc.z, acc.w);
        }
        __syncthreads();

        // coalesced write-out: row li_loc = t/8, 4 float4 per thread along lj
        const int li_loc = t >> 3;
        const int fq     = t & 7;
        const int i      = oti * TS + h * 32 + li_loc;
        #pragma unroll
        for (int r2 = 0; r2 < 4; ++r2) {
            int lj = (fq + 8 * r2) * 2;
            int j  = otj * TS + lj;
            if (i < ON && j < ON) {
                float2 e0 = sm[li_loc][lj];
                float2 e1 = sm[li_loc][lj + 1];
                *reinterpret_cast<float4*>(&out[((size_t)i * ON + j) * 2]) =
                    make_float4(e0.x, e0.y, e1.x, e1.y);
            }
        }
    }
}

} // namespace

extern "C" void kernel_launch(void* const* d_in, const int* in_sizes, int n_in,
                              void* d_out, int out_size)
{
    const float* x = nullptr;
    const float* W = nullptr;
    const float* b = nullptr;
    for (int i = 0; i < n_in; ++i) {
        if (in_sizes[i] == 512 * 1280)      x = (const float*)d_in[i];
        else if (in_sizes[i] == 2560 * 2)   W = (const float*)d_in[i];
        else if (in_sizes[i] == 2)          b = (const float*)d_in[i];
    }

    prep_kernel<<<Dd * (XTW / 4) / 256, 256>>>(x, W);   // 650 blocks
    contact_sym_kernel<<<dim3(NT, ZS), 256>>>();        // 288 CTAs
    reduce_kernel<<<dim3(2, 64), 256>>>(b, (float*)d_out);
}

// round 10
// speedup vs baseline: 2.1852x; 1.0136x over previous
#include <cuda_runtime.h>
#include <cstdint>

// out[i,j,k] = sum_d x[1+i,d] * x[1+j,d] * Wp[d,k] + b[k]   (symmetric in i,j)
// X: [512,1280] f32, Wp = W[:1280] of W:[2560,2], out: [510,510,2] f32.
//
// Two kernels only:
//  1) contact_sym_kernel: triangular 64x64 tiles (ti>=tj), D split into 8
//     z-slices. Fill = coalesced LDG of x rows + in-register W scaling +
//     transposed conflict-free STS (stride 72), register double-buffered.
//     FFMA2 inner loop. Partials to g_part.
//  2) reduce_kernel: tile-blocked slice sum + mirror (smem transpose) + bias.

namespace {

constexpr int Dd   = 1280;
constexpr int ON   = 510;
constexpr int TS   = 64;              // tile size
constexpr int KT   = 16;              // d per chunk
constexpr int SSTR = 72;              // smem row stride (conflict-free scatter STS)
constexpr int ZS   = 8;               // D slices (160 d each)
constexpr int DPZ  = Dd / ZS;
constexpr int NCH  = DPZ / KT;        // 10 chunks per slice
constexpr int NT   = 36;              // triangular tiles over 8x8
constexpr int TILE_ELEMS = TS * TS * 2;

__device__ float g_part[(size_t)ZS * NT * TILE_ELEMS];   // 9.4 MB partials

__device__ __forceinline__ void fma2(unsigned long long& acc,
                                     unsigned long long a,
                                     unsigned long long b) {
    asm("fma.rn.f32x2 %0, %1, %2, %0;" : "+l"(acc) : "l"(a), "l"(b));
}

__device__ __forceinline__ unsigned long long dup2(float v) {
    unsigned long long r;
    unsigned int u = __float_as_uint(v);
    asm("mov.b64 %0, {%1, %1};" : "=l"(r) : "r"(u));
    return r;
}

// ---------------- main symmetric GEMM with fused transpose fill ----------------
__global__ __launch_bounds__(256, 2)
void contact_sym_kernel(const float* __restrict__ x, const float* __restrict__ W)
{
    __shared__ float smA [2][KT][SSTR];
    __shared__ float smB0[2][KT][SSTR];
    __shared__ float smB1[2][KT][SSTR];

    const int tid = threadIdx.x;
    const int tx  = tid & 15;       // 16 j-groups of 4
    const int ty  = tid >> 4;       // 16 i-groups of 4

    // decode triangular tile id -> (ti, tj), ti >= tj
    int rem = blockIdx.x, ti = 0;
    while (rem > ti) { rem -= (ti + 1); ti++; }
    const int tj = rem;
    const int z  = blockIdx.y;

    const int ibase = ti * TS;
    const int jbase = tj * TS;
    const int dbase = z * DPZ;

    // fill mapping: r = row within tile, dq = d offset (0,4,8,12)
    const int fr = tid >> 2;              // 0..63
    const int dq = (tid & 3) * 4;

    const int gi = ibase + fr;            // output row index of A element
    const int gj = jbase + fr;
    const bool vi = (gi < 511);           // x row gi+1 valid (only gi==511 invalid)
    const bool vj = (gj < 511);

    const float* __restrict__ xa = x + (size_t)(gi + 1) * Dd + dbase + dq;
    const float* __restrict__ xb = x + (size_t)(gj + 1) * Dd + dbase + dq;
    // W as float2[d]; 4 consecutive d = 2 float4
    const float4* __restrict__ wp = reinterpret_cast<const float4*>(W + 2 * (dbase + dq));

    unsigned long long acc[2][4][2];
    #pragma unroll
    for (int k = 0; k < 2; ++k)
        #pragma unroll
        for (int ii = 0; ii < 4; ++ii)
            #pragma unroll
            for (int jp = 0; jp < 2; ++jp)
                acc[k][ii][jp] = 0ull;

    float4 rA, rB, rW0, rW1;

    // prologue: load chunk 0 into registers, store to buffer 0
    {
        rA  = vi ? *reinterpret_cast<const float4*>(xa) : make_float4(0,0,0,0);
        rB  = vj ? *reinterpret_cast<const float4*>(xb) : make_float4(0,0,0,0);
        rW0 = wp[0];      // (w0[d],w1[d], w0[d+1],w1[d+1])
        rW1 = wp[1];      // (w0[d+2],w1[d+2], w0[d+3],w1[d+3])

        smA [0][dq + 0][fr] = rA.x;
        smA [0][dq + 1][fr] = rA.y;
        smA [0][dq + 2][fr] = rA.z;
        smA [0][dq + 3][fr] = rA.w;
        smB0[0][dq + 0][fr] = rB.x * rW0.x;  smB1[0][dq + 0][fr] = rB.x * rW0.y;
        smB0[0][dq + 1][fr] = rB.y * rW0.z;  smB1[0][dq + 1][fr] = rB.y * rW0.w;
        smB0[0][dq + 2][fr] = rB.z * rW1.x;  smB1[0][dq + 2][fr] = rB.z * rW1.y;
        smB0[0][dq + 3][fr] = rB.w * rW1.z;  smB1[0][dq + 3][fr] = rB.w * rW1.w;
    }
    __syncthreads();

    for (int c = 0; c < NCH; ++c) {
        const bool more = (c + 1 < NCH);
        if (more) {
            const size_t off = (size_t)(c + 1) * KT;
            rA  = vi ? *reinterpret_cast<const float4*>(xa + off) : make_float4(0,0,0,0);
            rB  = vj ? *reinterpret_cast<const float4*>(xb + off) : make_float4(0,0,0,0);
            const float4* wpn = reinterpret_cast<const float4*>(
                W + 2 * (dbase + (c + 1) * KT + dq));
            rW0 = wpn[0];
            rW1 = wpn[1];
        }

        const int cb = c & 1;
        #pragma unroll
        for (int d = 0; d < KT; ++d) {
            float4 av = *reinterpret_cast<const float4*>(&smA[cb][d][4 * ty]);
            unsigned long long A0 = dup2(av.x);
            unsigned long long A1 = dup2(av.y);
            unsigned long long A2 = dup2(av.z);
            unsigned long long A3 = dup2(av.w);

            ulonglong2 B0 = *reinterpret_cast<const ulonglong2*>(&smB0[cb][d][4 * tx]);
            ulonglong2 B1 = *reinterpret_cast<const ulonglong2*>(&smB1[cb][d][4 * tx]);

            fma2(acc[0][0][0], A0, B0.x);  fma2(acc[0][0][1], A0, B0.y);
            fma2(acc[0][1][0], A1, B0.x);  fma2(acc[0][1][1], A1, B0.y);
            fma2(acc[0][2][0], A2, B0.x);  fma2(acc[0][2][1], A2, B0.y);
            fma2(acc[0][3][0], A3, B0.x);  fma2(acc[0][3][1], A3, B0.y);
            fma2(acc[1][0][0], A0, B1.x);  fma2(acc[1][0][1], A0, B1.y);
            fma2(acc[1][1][0], A1, B1.x);  fma2(acc[1][1][1], A1, B1.y);
            fma2(acc[1][2][0], A2, B1.x);  fma2(acc[1][2][1], A2, B1.y);
            fma2(acc[1][3][0], A3, B1.x);  fma2(acc[1][3][1], A3, B1.y);
        }

        if (more) {
            const int nb = cb ^ 1;
            smA [nb][dq + 0][fr] = rA.x;
            smA [nb][dq + 1][fr] = rA.y;
            smA [nb][dq + 2][fr] = rA.z;
            smA [nb][dq + 3][fr] = rA.w;
            smB0[nb][dq + 0][fr] = rB.x * rW0.x;  smB1[nb][dq + 0][fr] = rB.x * rW0.y;
            smB0[nb][dq + 1][fr] = rB.y * rW0.z;  smB1[nb][dq + 1][fr] = rB.y * rW0.w;
            smB0[nb][dq + 2][fr] = rB.z * rW1.x;  smB1[nb][dq + 2][fr] = rB.z * rW1.y;
            smB0[nb][dq + 3][fr] = rB.w * rW1.z;  smB1[nb][dq + 3][fr] = rB.w * rW1.w;
            __syncthreads();
        }
    }

    // epilogue: partials to scratch, k-interleaved [li][lj][k]
    float* __restrict__ s = g_part + ((size_t)z * NT + blockIdx.x) * TILE_ELEMS;
    const int lj0 = 4 * tx;
    #pragma unroll
    for (int ii = 0; ii < 4; ++ii) {
        const int li = 4 * ty + ii;
        #pragma unroll
        for (int jp = 0; jp < 2; ++jp) {
            unsigned int k0e, k0o, k1e, k1o;
            asm("mov.b64 {%0, %1}, %2;" : "=r"(k0e), "=r"(k0o) : "l"(acc[0][ii][jp]));
            asm("mov.b64 {%0, %1}, %2;" : "=r"(k1e), "=r"(k1o) : "l"(acc[1][ii][jp]));
            float4 v = make_float4(__uint_as_float(k0e), __uint_as_float(k1e),
                                   __uint_as_float(k0o), __uint_as_float(k1o));
            *reinterpret_cast<float4*>(&s[((size_t)li * TS + lj0 + 2 * jp) * 2]) = v;
        }
    }
}

// ---------------- reduce: tile-blocked slice sum + mirror + bias ----------------
__global__ __launch_bounds__(256)
void reduce_kernel(const float* __restrict__ bvec, float* __restrict__ out)
{
    __shared__ float2 sm[32][67];    // padded transpose buffer (mirror path)

    const int t   = threadIdx.x;
    const int h   = blockIdx.x;            // 0/1: row half
    const int ot  = blockIdx.y;            // output tile id
    const int oti = ot >> 3;
    const int otj = ot & 7;

    const float b0 = bvec[0];
    const float b1 = bvec[1];

    if (oti >= otj) {
        const int src = (oti * (oti + 1)) / 2 + otj;
        const float* base = g_part + (size_t)src * TILE_ELEMS;
        #pragma unroll
        for (int r = 0; r < 4; ++r) {
            int fp = t + 256 * r;
            int a  = h * 32 + (fp >> 5);
            int lj = (fp & 31) * 2;
            size_t off = ((size_t)a * TS + lj) * 2;

            float4 acc = make_float4(b0, b1, b0, b1);
            #pragma unroll
            for (int z = 0; z < ZS; ++z) {
                float4 v = *reinterpret_cast<const float4*>(
                    base + (size_t)z * NT * TILE_ELEMS + off);
                acc.x += v.x; acc.y += v.y; acc.z += v.z; acc.w += v.w;
            }
            int i = oti * TS + a;
            int j = otj * TS + lj;
            if (i < ON && j < ON)
                *reinterpret_cast<float4*>(&out[((size_t)i * ON + j) * 2]) = acc;
        }
    } else {
        const int src = (otj * (otj + 1)) / 2 + oti;
        const float* base = g_part + (size_t)src * TILE_ELEMS;
        #pragma unroll
        for (int r = 0; r < 4; ++r) {
            int fp = t + 256 * r;
            int b  = fp >> 4;                     // src row (= out col lj)
            int c  = fp & 15;
            int a0 = h * 32 + c * 2;              // src cols (= out rows li)
            size_t off = ((size_t)b * TS + a0) * 2;

            float4 acc = make_float4(b0, b1, b0, b1);
            #pragma unroll
            for (int z = 0; z < ZS; ++z) {
                float4 v = *reinterpret_cast<const float4*>(
                    base + (size_t)z * NT * TILE_ELEMS + off);
                acc.x += v.x; acc.y += v.y; acc.z += v.z; acc.w += v.w;
            }
            sm[c * 2 + 0][b] = make_float2(acc.x, acc.y);
            sm[c * 2 + 1][b] = make_float2(acc.z, acc.w);
        }
        __syncthreads();

        const int li_loc = t >> 3;
        const int fq     = t & 7;
        const int i      = oti * TS + h * 32 + li_loc;
        #pragma unroll
        for (int r2 = 0; r2 < 4; ++r2) {
            int lj = (fq + 8 * r2) * 2;
            int j  = otj * TS + lj;
            if (i < ON && j < ON) {
                float2 e0 = sm[li_loc][lj];
                float2 e1 = sm[li_loc][lj + 1];
                *reinterpret_cast<float4*>(&out[((size_t)i * ON + j) * 2]) =
                    make_float4(e0.x, e0.y, e1.x, e1.y);
            }
        }
    }
}

} // namespace

extern "C" void kernel_launch(void* const* d_in, const int* in_sizes, int n_in,
                              void* d_out, int out_size)
{
    const float* x = nullptr;
    const float* W = nullptr;
    const float* b = nullptr;
    for (int i = 0; i < n_in; ++i) {
        if (in_sizes[i] == 512 * 1280)      x = (const float*)d_in[i];
        else if (in_sizes[i] == 2560 * 2)   W = (const float*)d_in[i];
        else if (in_sizes[i] == 2)          b = (const float*)d_in[i];
    }

    contact_sym_kernel<<<dim3(NT, ZS), 256>>>(x, W);     // 288 CTAs
    reduce_kernel<<<dim3(2, 64), 256>>>(b, (float*)d_out);
}

// round 11
// speedup vs baseline: 2.6470x; 1.2113x over previous
#include <cuda_runtime.h>
#include <cstdint>

// out[i,j,k] = sum_d x[1+i,d] * x[1+j,d] * Wp[d,k] + b[k]   (symmetric in i,j)
// X: [512,1280] f32, Wp = W[:1280] of W:[2560,2], out: [510,510,2] f32.
//
// Two kernels:
//  1) contact_sym_kernel: triangular 64x64 tiles (ti>=tj), D split into 8
//     z-slices. Fill: coalesced LDG + in-register W scaling + transposed STS
//     (stride 68, 2-way max), register double-buffered. 2-D warp tiling
//     (each warp owns 32i x 16j) to minimize smem crossbar traffic.
//     FFMA2 inner loop. Partials to g_part.
//  2) reduce_kernel: 256 CTAs, tile-blocked slice sum + mirror transpose + bias.

namespace {

constexpr int Dd   = 1280;
constexpr int ON   = 510;
constexpr int TS   = 64;              // tile size
constexpr int KT   = 16;              // d per chunk
constexpr int SSTR = 68;              // smem row stride (2-way max on scatter STS)
constexpr int ZS   = 8;               // D slices (160 d each)
constexpr int DPZ  = Dd / ZS;
constexpr int NCH  = DPZ / KT;        // 10 chunks per slice
constexpr int NT   = 36;              // triangular tiles over 8x8
constexpr int TILE_ELEMS = TS * TS * 2;

__device__ float g_part[(size_t)ZS * NT * TILE_ELEMS];   // 9.4 MB partials

__device__ __forceinline__ void fma2(unsigned long long& acc,
                                     unsigned long long a,
                                     unsigned long long b) {
    asm("fma.rn.f32x2 %0, %1, %2, %0;" : "+l"(acc) : "l"(a), "l"(b));
}

__device__ __forceinline__ unsigned long long dup2(float v) {
    unsigned long long r;
    unsigned int u = __float_as_uint(v);
    asm("mov.b64 %0, {%1, %1};" : "=l"(r) : "r"(u));
    return r;
}

// ---------------- main symmetric GEMM with fused transpose fill ----------------
__global__ __launch_bounds__(256, 2)
void contact_sym_kernel(const float* __restrict__ x, const float* __restrict__ W)
{
    __shared__ float smA [2][KT][SSTR];
    __shared__ float smB0[2][KT][SSTR];
    __shared__ float smB1[2][KT][SSTR];

    const int tid  = threadIdx.x;
    const int lane = tid & 31;
    const int w    = tid >> 5;
    // 2-D warp tiling: warp owns 32i x 16j -> 256B unique LDS per warp-d.
    const int ty = (w & 1) * 8 + (lane & 7);    // i group (0..15), 4 i each
    const int tx = (w >> 1) * 4 + (lane >> 3);  // j group (0..15), 4 j each

    // decode triangular tile id -> (ti, tj), ti >= tj
    int rem = blockIdx.x, ti = 0;
    while (rem > ti) { rem -= (ti + 1); ti++; }
    const int tj = rem;
    const int z  = blockIdx.y;

    const int ibase = ti * TS;
    const int jbase = tj * TS;
    const int dbase = z * DPZ;

    // fill mapping: fr = row within tile, dq = d offset (0,4,8,12)
    const int fr = tid >> 2;              // 0..63
    const int dq = (tid & 3) * 4;

    const int gi = ibase + fr;
    const int gj = jbase + fr;
    const bool vi = (gi < 511);           // x row gi+1 valid
    const bool vj = (gj < 511);

    const float* __restrict__ xa = x + (size_t)(gi + 1) * Dd + dbase + dq;
    const float* __restrict__ xb = x + (size_t)(gj + 1) * Dd + dbase + dq;
    const float4* __restrict__ wp = reinterpret_cast<const float4*>(W + 2 * (dbase + dq));

    unsigned long long acc[2][4][2];
    #pragma unroll
    for (int k = 0; k < 2; ++k)
        #pragma unroll
        for (int ii = 0; ii < 4; ++ii)
            #pragma unroll
            for (int jp = 0; jp < 2; ++jp)
                acc[k][ii][jp] = 0ull;

    float4 rA, rB, rW0, rW1;

    // prologue: chunk 0 -> buffer 0
    {
        rA  = vi ? *reinterpret_cast<const float4*>(xa) : make_float4(0,0,0,0);
        rB  = vj ? *reinterpret_cast<const float4*>(xb) : make_float4(0,0,0,0);
        rW0 = wp[0];
        rW1 = wp[1];

        smA [0][dq + 0][fr] = rA.x;
        smA [0][dq + 1][fr] = rA.y;
        smA [0][dq + 2][fr] = rA.z;
        smA [0][dq + 3][fr] = rA.w;
        smB0[0][dq + 0][fr] = rB.x * rW0.x;  smB1[0][dq + 0][fr] = rB.x * rW0.y;
        smB0[0][dq + 1][fr] = rB.y * rW0.z;  smB1[0][dq + 1][fr] = rB.y * rW0.w;
        smB0[0][dq + 2][fr] = rB.z * rW1.x;  smB1[0][dq + 2][fr] = rB.z * rW1.y;
        smB0[0][dq + 3][fr] = rB.w * rW1.z;  smB1[0][dq + 3][fr] = rB.w * rW1.w;
    }
    __syncthreads();

    for (int c = 0; c < NCH; ++c) {
        const bool more = (c + 1 < NCH);
        if (more) {
            const size_t off = (size_t)(c + 1) * KT;
            rA  = vi ? *reinterpret_cast<const float4*>(xa + off) : make_float4(0,0,0,0);
            rB  = vj ? *reinterpret_cast<const float4*>(xb + off) : make_float4(0,0,0,0);
            const float4* wpn = reinterpret_cast<const float4*>(
                W + 2 * (dbase + (c + 1) * KT + dq));
            rW0 = wpn[0];
            rW1 = wpn[1];
        }

        const int cb = c & 1;
        #pragma unroll
        for (int d = 0; d < KT; ++d) {
            float4 av = *reinterpret_cast<const float4*>(&smA[cb][d][4 * ty]);
            unsigned long long A0 = dup2(av.x);
            unsigned long long A1 = dup2(av.y);
            unsigned long long A2 = dup2(av.z);
            unsigned long long A3 = dup2(av.w);

            ulonglong2 B0 = *reinterpret_cast<const ulonglong2*>(&smB0[cb][d][4 * tx]);
            ulonglong2 B1 = *reinterpret_cast<const ulonglong2*>(&smB1[cb][d][4 * tx]);

            fma2(acc[0][0][0], A0, B0.x);  fma2(acc[0][0][1], A0, B0.y);
            fma2(acc[0][1][0], A1, B0.x);  fma2(acc[0][1][1], A1, B0.y);
            fma2(acc[0][2][0], A2, B0.x);  fma2(acc[0][2][1], A2, B0.y);
            fma2(acc[0][3][0], A3, B0.x);  fma2(acc[0][3][1], A3, B0.y);
            fma2(acc[1][0][0], A0, B1.x);  fma2(acc[1][0][1], A0, B1.y);
            fma2(acc[1][1][0], A1, B1.x);  fma2(acc[1][1][1], A1, B1.y);
            fma2(acc[1][2][0], A2, B1.x);  fma2(acc[1][2][1], A2, B1.y);
            fma2(acc[1][3][0], A3, B1.x);  fma2(acc[1][3][1], A3, B1.y);
        }

        if (more) {
            const int nb = cb ^ 1;
            smA [nb][dq + 0][fr] = rA.x;
            smA [nb][dq + 1][fr] = rA.y;
            smA [nb][dq + 2][fr] = rA.z;
            smA [nb][dq + 3][fr] = rA.w;
            smB0[nb][dq + 0][fr] = rB.x * rW0.x;  smB1[nb][dq + 0][fr] = rB.x * rW0.y;
            smB0[nb][dq + 1][fr] = rB.y * rW0.z;  smB1[nb][dq + 1][fr] = rB.y * rW0.w;
            smB0[nb][dq + 2][fr] = rB.z * rW1.x;  smB1[nb][dq + 2][fr] = rB.z * rW1.y;
            smB0[nb][dq + 3][fr] = rB.w * rW1.z;  smB1[nb][dq + 3][fr] = rB.w * rW1.w;
            __syncthreads();
        }
    }

    // epilogue: partials to scratch, k-interleaved [li][lj][k]
    float* __restrict__ s = g_part + ((size_t)z * NT + blockIdx.x) * TILE_ELEMS;
    const int lj0 = 4 * tx;
    #pragma unroll
    for (int ii = 0; ii < 4; ++ii) {
        const int li = 4 * ty + ii;
        #pragma unroll
        for (int jp = 0; jp < 2; ++jp) {
            unsigned int k0e, k0o, k1e, k1o;
            asm("mov.b64 {%0, %1}, %2;" : "=r"(k0e), "=r"(k0o) : "l"(acc[0][ii][jp]));
            asm("mov.b64 {%0, %1}, %2;" : "=r"(k1e), "=r"(k1o) : "l"(acc[1][ii][jp]));
            float4 v = make_float4(__uint_as_float(k0e), __uint_as_float(k1e),
                                   __uint_as_float(k0o), __uint_as_float(k1o));
            *reinterpret_cast<float4*>(&s[((size_t)li * TS + lj0 + 2 * jp) * 2]) = v;
        }
    }
}

// ---------------- reduce: 256 CTAs, slice sum + mirror + bias ----------------
// grid = (4 quarters of 16 rows, 64 output tiles); block = 256 threads.
__global__ __launch_bounds__(256)
void reduce_kernel(const float* __restrict__ bvec, float* __restrict__ out)
{
    __shared__ float2 sm[16][67];    // padded transpose buffer (mirror path)

    const int t   = threadIdx.x;
    const int h   = blockIdx.x;            // 0..3: 16-row slice
    const int ot  = blockIdx.y;            // output tile id
    const int oti = ot >> 3;
    const int otj = ot & 7;

    const float b0 = bvec[0];
    const float b1 = bvec[1];

    if (oti >= otj) {
        const int src = (oti * (oti + 1)) / 2 + otj;
        const float* base = g_part + (size_t)src * TILE_ELEMS;
        #pragma unroll
        for (int r = 0; r < 2; ++r) {
            int fp = t + 256 * r;                 // 0..511
            int a  = h * 16 + (fp >> 5);          // row li
            int lj = (fp & 31) * 2;               // col pair
            size_t off = ((size_t)a * TS + lj) * 2;

            float4 acc = make_float4(b0, b1, b0, b1);
            #pragma unroll
            for (int z = 0; z < ZS; ++z) {
                float4 v = *reinterpret_cast<const float4*>(
                    base + (size_t)z * NT * TILE_ELEMS + off);
                acc.x += v.x; acc.y += v.y; acc.z += v.z; acc.w += v.w;
            }
            int i = oti * TS + a;
            int j = otj * TS + lj;
            if (i < ON && j < ON)
                *reinterpret_cast<float4*>(&out[((size_t)i * ON + j) * 2]) = acc;
        }
    } else {
        // mirror: source tile (otj,oti); out[li][lj] = src[lj][li]
        const int src = (otj * (otj + 1)) / 2 + oti;
        const float* base = g_part + (size_t)src * TILE_ELEMS;
        #pragma unroll
        for (int r = 0; r < 2; ++r) {
            int fp = t + 256 * r;                 // 0..511
            int b  = fp >> 3;                     // src row (= out col lj), 0..63
            int c  = fp & 7;                      // col-pair group within slice
            int a0 = h * 16 + c * 2;              // src cols (= out rows li)
            size_t off = ((size_t)b * TS + a0) * 2;

            float4 acc = make_float4(b0, b1, b0, b1);
            #pragma unroll
            for (int z = 0; z < ZS; ++z) {
                float4 v = *reinterpret_cast<const float4*>(
                    base + (size_t)z * NT * TILE_ELEMS + off);
                acc.x += v.x; acc.y += v.y; acc.z += v.z; acc.w += v.w;
            }
            sm[c * 2 + 0][b] = make_float2(acc.x, acc.y);
            sm[c * 2 + 1][b] = make_float2(acc.z, acc.w);
        }
        __syncthreads();

        // coalesced write-out: row li_loc = t/16, 2 float4 per thread along lj
        const int li_loc = t >> 4;               // 0..15
        const int fq     = t & 15;
        const int i      = oti * TS + h * 16 + li_loc;
        #pragma unroll
        for (int r2 = 0; r2 < 2; ++r2) {
            int lj = (fq + 16 * r2) * 2;
            int j  = otj * TS + lj;
            if (i < ON && j < ON) {
                float2 e0 = sm[li_loc][lj];
                float2 e1 = sm[li_loc][lj + 1];
                *reinterpret_cast<float4*>(&out[((size_t)i * ON + j) * 2]) =
                    make_float4(e0.x, e0.y, e1.x, e1.y);
            }
        }
    }
}

} // namespace

extern "C" void kernel_launch(void* const* d_in, const int* in_sizes, int n_in,
                              void* d_out, int out_size)
{
    const float* x = nullptr;
    const float* W = nullptr;
    const float* b = nullptr;
    for (int i = 0; i < n_in; ++i) {
        if (in_sizes[i] == 512 * 1280)      x = (const float*)d_in[i];
        else if (in_sizes[i] == 2560 * 2)   W = (const float*)d_in[i];
        else if (in_sizes[i] == 2)          b = (const float*)d_in[i];
    }

    contact_sym_kernel<<<dim3(NT, ZS), 256>>>(x, W);     // 288 CTAs
    reduce_kernel<<<dim3(4, 64), 256>>>(b, (float*)d_out);
}